// round 1
// baseline (speedup 1.0000x reference)
#include <cuda_runtime.h>
#include <math.h>

#define Bb 2
#define Ts 2048
#define Dd 1024
#define Hh 16
#define DHd 64
#define MROWS (Bb*Ts)   // 4096

// Scratch (allocation-free rule: __device__ globals)
__device__ float g_qkv[(size_t)MROWS * 3 * Dd];      // [B*T, 3D]
__device__ float g_q[(size_t)Bb * Hh * Ts * DHd];    // [B,H,T,DH]
__device__ float g_k[(size_t)Bb * Hh * Ts * DHd];
__device__ float g_v[(size_t)Bb * Hh * Ts * DHd];
__device__ float g_attn[(size_t)MROWS * Dd];         // [B*T, D]

// ---------------------------------------------------------------------------
// SGEMM: C[M,N] = A[M,K] @ B[K,N], row-major, all dims multiples of tile sizes
// 128x128 block tile, BK=8, 8x8 per-thread microtile, 256 threads.
// ---------------------------------------------------------------------------
__global__ __launch_bounds__(256) void sgemm128(const float* __restrict__ A,
                                                const float* __restrict__ Bw,
                                                float* __restrict__ C,
                                                int M, int N, int K) {
    constexpr int BM = 128, BN = 128, BK = 8;
    __shared__ float As[BK][BM];
    __shared__ float Bs[BK][BN];

    const int tid = threadIdx.x;
    const int bx = blockIdx.x, by = blockIdx.y;
    const int tx = tid & 15;       // 0..15 (N dir)
    const int ty = tid >> 4;       // 0..15 (M dir)

    const int arow = tid >> 1;            // 0..127
    const int acol = (tid & 1) * 4;       // 0 or 4
    const int brow = tid >> 5;            // 0..7
    const int bcol = (tid & 31) * 4;      // 0..124

    const float* Ap = A + (size_t)(by * BM + arow) * K + acol;
    const float* Bp = Bw + (size_t)brow * N + bx * BN + bcol;

    float acc[8][8];
    #pragma unroll
    for (int i = 0; i < 8; i++)
        #pragma unroll
        for (int j = 0; j < 8; j++) acc[i][j] = 0.0f;

    for (int k0 = 0; k0 < K; k0 += BK) {
        float4 a4 = *(const float4*)Ap;
        float4 b4 = *(const float4*)Bp;
        As[acol + 0][arow] = a4.x;
        As[acol + 1][arow] = a4.y;
        As[acol + 2][arow] = a4.z;
        As[acol + 3][arow] = a4.w;
        *(float4*)&Bs[brow][bcol] = b4;
        __syncthreads();

        #pragma unroll
        for (int kk = 0; kk < BK; kk++) {
            float am[8], bn[8];
            *(float4*)&am[0] = *(const float4*)&As[kk][ty * 8];
            *(float4*)&am[4] = *(const float4*)&As[kk][ty * 8 + 4];
            *(float4*)&bn[0] = *(const float4*)&Bs[kk][tx * 8];
            *(float4*)&bn[4] = *(const float4*)&Bs[kk][tx * 8 + 4];
            #pragma unroll
            for (int i = 0; i < 8; i++)
                #pragma unroll
                for (int j = 0; j < 8; j++)
                    acc[i][j] = fmaf(am[i], bn[j], acc[i][j]);
        }
        __syncthreads();
        Ap += BK;
        Bp += (size_t)BK * N;
    }

    float* Cp = C + (size_t)(by * BM + ty * 8) * N + bx * BN + tx * 8;
    #pragma unroll
    for (int i = 0; i < 8; i++) {
        *(float4*)(Cp + (size_t)i * N) =
            make_float4(acc[i][0], acc[i][1], acc[i][2], acc[i][3]);
        *(float4*)(Cp + (size_t)i * N + 4) =
            make_float4(acc[i][4], acc[i][5], acc[i][6], acc[i][7]);
    }
}

// ---------------------------------------------------------------------------
// RoPE + split/transpose: qkv [B,T,3,H,DH] -> q/k (roped), v  as [B,H,T,DH]
// ---------------------------------------------------------------------------
__global__ __launch_bounds__(256) void rope_split_kernel(
    const float* __restrict__ qkv,
    float* __restrict__ qo, float* __restrict__ ko, float* __restrict__ vo) {
    int idx = blockIdx.x * blockDim.x + threadIdx.x;   // over B*H*T*DH = 4M
    int d = idx & 63;
    int t = (idx >> 6) & (Ts - 1);
    int h = (idx >> 17) & (Hh - 1);
    int b = idx >> 21;

    size_t base = ((size_t)(b * Ts + t)) * (3 * Dd) + h * DHd;
    float qv = qkv[base + d];
    float kv = qkv[base + Dd + d];
    float vv = qkv[base + 2 * Dd + d];

    int d2 = (d < 32) ? d + 32 : d - 32;
    float sgn = (d < 32) ? -1.0f : 1.0f;
    float qp = qkv[base + d2] * sgn;
    float kp = qkv[base + Dd + d2] * sgn;

    int fidx = d & 31;
    // inv_freq = 10000^(-fidx/32) computed accurately, then fp32 like the ref
    float inv = (float)exp2(-(double)fidx / 32.0 * 13.287712379549449);  // log2(10000)
    float ang = (float)t * inv;
    float c, s;
    sincosf(ang, &s, &c);

    size_t oidx = (((size_t)(b * Hh + h)) * Ts + t) * DHd + d;
    qo[oidx] = qv * c + qp * s;
    ko[oidx] = kv * c + kp * s;
    vo[oidx] = vv;
}

// ---------------------------------------------------------------------------
// Causal attention, one thread per query row, streaming softmax.
// block = 128 threads = 128 query rows; K/V staged in smem 64 keys at a time.
// ---------------------------------------------------------------------------
__global__ __launch_bounds__(128) void attn_kernel(
    const float* __restrict__ q, const float* __restrict__ k,
    const float* __restrict__ v, float* __restrict__ out) {
    const int qt = blockIdx.x;     // 0..15
    const int h  = blockIdx.y;
    const int b  = blockIdx.z;
    const int tid = threadIdx.x;
    const int qi = qt * 128 + tid;
    const float scale = 0.125f;    // 1/sqrt(64)

    __shared__ float4 Ks[64][16];
    __shared__ float4 Vs[64][16];

    const size_t head_off = ((size_t)(b * Hh + h)) * Ts * DHd;
    const float* qptr = q + head_off + (size_t)qi * DHd;
    const float* kbase = k + head_off;
    const float* vbase = v + head_off;

    float4 qr[16];
    #pragma unroll
    for (int i = 0; i < 16; i++) qr[i] = ((const float4*)qptr)[i];

    float4 o4[16];
    #pragma unroll
    for (int i = 0; i < 16; i++) o4[i] = make_float4(0.f, 0.f, 0.f, 0.f);
    float m = -INFINITY, l = 0.0f;

    const int ktiles = 2 * qt + 2;   // tiles 0 .. 2qt+1 cover keys <= qt*128+127
    for (int kt = 0; kt < ktiles; kt++) {
        __syncthreads();
        #pragma unroll 4
        for (int i = tid; i < 64 * 16; i += 128) {
            int r = i >> 4, c = i & 15;
            Ks[r][c] = ((const float4*)(kbase + (size_t)(kt * 64 + r) * DHd))[c];
            Vs[r][c] = ((const float4*)(vbase + (size_t)(kt * 64 + r) * DHd))[c];
        }
        __syncthreads();

        int jmax = qi - kt * 64 + 1;          // causal bound for this thread
        if (jmax > 64) jmax = 64;
        for (int j = 0; j < jmax; j++) {
            float s = 0.0f;
            #pragma unroll
            for (int i = 0; i < 16; i++) {
                float4 kv4 = Ks[j][i];
                s = fmaf(qr[i].x, kv4.x, s);
                s = fmaf(qr[i].y, kv4.y, s);
                s = fmaf(qr[i].z, kv4.z, s);
                s = fmaf(qr[i].w, kv4.w, s);
            }
            s *= scale;
            if (s > m) {                       // rare-max path: rescale state
                float corr = __expf(m - s);    // exp(-inf)=0 on first key
                l *= corr;
                #pragma unroll
                for (int i = 0; i < 16; i++) {
                    o4[i].x *= corr; o4[i].y *= corr;
                    o4[i].z *= corr; o4[i].w *= corr;
                }
                m = s;
            }
            float p = __expf(s - m);
            l += p;
            #pragma unroll
            for (int i = 0; i < 16; i++) {
                float4 vv4 = Vs[j][i];
                o4[i].x = fmaf(p, vv4.x, o4[i].x);
                o4[i].y = fmaf(p, vv4.y, o4[i].y);
                o4[i].z = fmaf(p, vv4.z, o4[i].z);
                o4[i].w = fmaf(p, vv4.w, o4[i].w);
            }
        }
    }

    float invl = 1.0f / l;
    float* optr = out + ((size_t)(b * Ts + qi)) * Dd + h * DHd;
    #pragma unroll
    for (int i = 0; i < 16; i++) {
        float4 r = o4[i];
        r.x *= invl; r.y *= invl; r.z *= invl; r.w *= invl;
        ((float4*)optr)[i] = r;
    }
}

// ---------------------------------------------------------------------------
extern "C" void kernel_launch(void* const* d_in, const int* in_sizes, int n_in,
                              void* d_out, int out_size) {
    const float* x     = (const float*)d_in[0];
    const float* w_qkv = (const float*)d_in[1];
    const float* w_out = (const float*)d_in[2];
    float* out = (float*)d_out;

    float *qkv, *q, *k, *v, *attn;
    cudaGetSymbolAddress((void**)&qkv,  g_qkv);
    cudaGetSymbolAddress((void**)&q,    g_q);
    cudaGetSymbolAddress((void**)&k,    g_k);
    cudaGetSymbolAddress((void**)&v,    g_v);
    cudaGetSymbolAddress((void**)&attn, g_attn);

    // 1) QKV projection: [4096,1024] @ [1024,3072]
    sgemm128<<<dim3((3 * Dd) / 128, MROWS / 128), 256>>>(x, w_qkv, qkv,
                                                         MROWS, 3 * Dd, Dd);
    // 2) RoPE + split to [B,H,T,DH]
    rope_split_kernel<<<(Bb * Hh * Ts * DHd) / 256, 256>>>(qkv, q, k, v);
    // 3) causal attention -> [B,T,D]
    attn_kernel<<<dim3(Ts / 128, Hh, Bb), 128>>>(q, k, v, attn);
    // 4) output projection: [4096,1024] @ [1024,1024]
    sgemm128<<<dim3(Dd / 128, MROWS / 128), 256>>>(attn, w_out, out,
                                                   MROWS, Dd, Dd);
}

// round 2
// speedup vs baseline: 1.1907x; 1.1907x over previous
#include <cuda_runtime.h>
#include <math.h>

#define Bb 2
#define Ts 2048
#define Dd 1024
#define Hh 16
#define DHd 64
#define MROWS (Bb*Ts)   // 4096

// Scratch (allocation-free rule: __device__ globals)
__device__ float g_qkv[(size_t)MROWS * 3 * Dd];      // [B*T, 3D]
__device__ float g_q[(size_t)Bb * Hh * Ts * DHd];    // [B,H,T,DH]
__device__ float g_k[(size_t)Bb * Hh * Ts * DHd];
__device__ float g_v[(size_t)Bb * Hh * Ts * DHd];
__device__ float g_attn[(size_t)MROWS * Dd];         // [B*T, D]

// ---------------------------------------------------------------------------
// SGEMM: C[M,N] = A[M,K] @ B[K,N] (unchanged from round 1)
// ---------------------------------------------------------------------------
__global__ __launch_bounds__(256) void sgemm128(const float* __restrict__ A,
                                                const float* __restrict__ Bw,
                                                float* __restrict__ C,
                                                int M, int N, int K) {
    constexpr int BM = 128, BN = 128, BK = 8;
    __shared__ float As[BK][BM];
    __shared__ float Bs[BK][BN];

    const int tid = threadIdx.x;
    const int bx = blockIdx.x, by = blockIdx.y;
    const int tx = tid & 15;
    const int ty = tid >> 4;

    const int arow = tid >> 1;
    const int acol = (tid & 1) * 4;
    const int brow = tid >> 5;
    const int bcol = (tid & 31) * 4;

    const float* Ap = A + (size_t)(by * BM + arow) * K + acol;
    const float* Bp = Bw + (size_t)brow * N + bx * BN + bcol;

    float acc[8][8];
    #pragma unroll
    for (int i = 0; i < 8; i++)
        #pragma unroll
        for (int j = 0; j < 8; j++) acc[i][j] = 0.0f;

    for (int k0 = 0; k0 < K; k0 += BK) {
        float4 a4 = *(const float4*)Ap;
        float4 b4 = *(const float4*)Bp;
        As[acol + 0][arow] = a4.x;
        As[acol + 1][arow] = a4.y;
        As[acol + 2][arow] = a4.z;
        As[acol + 3][arow] = a4.w;
        *(float4*)&Bs[brow][bcol] = b4;
        __syncthreads();

        #pragma unroll
        for (int kk = 0; kk < BK; kk++) {
            float am[8], bn[8];
            *(float4*)&am[0] = *(const float4*)&As[kk][ty * 8];
            *(float4*)&am[4] = *(const float4*)&As[kk][ty * 8 + 4];
            *(float4*)&bn[0] = *(const float4*)&Bs[kk][tx * 8];
            *(float4*)&bn[4] = *(const float4*)&Bs[kk][tx * 8 + 4];
            #pragma unroll
            for (int i = 0; i < 8; i++)
                #pragma unroll
                for (int j = 0; j < 8; j++)
                    acc[i][j] = fmaf(am[i], bn[j], acc[i][j]);
        }
        __syncthreads();
        Ap += BK;
        Bp += (size_t)BK * N;
    }

    float* Cp = C + (size_t)(by * BM + ty * 8) * N + bx * BN + tx * 8;
    #pragma unroll
    for (int i = 0; i < 8; i++) {
        *(float4*)(Cp + (size_t)i * N) =
            make_float4(acc[i][0], acc[i][1], acc[i][2], acc[i][3]);
        *(float4*)(Cp + (size_t)i * N + 4) =
            make_float4(acc[i][4], acc[i][5], acc[i][6], acc[i][7]);
    }
}

// ---------------------------------------------------------------------------
// RoPE + split/transpose (unchanged)
// ---------------------------------------------------------------------------
__global__ __launch_bounds__(256) void rope_split_kernel(
    const float* __restrict__ qkv,
    float* __restrict__ qo, float* __restrict__ ko, float* __restrict__ vo) {
    int idx = blockIdx.x * blockDim.x + threadIdx.x;
    int d = idx & 63;
    int t = (idx >> 6) & (Ts - 1);
    int h = (idx >> 17) & (Hh - 1);
    int b = idx >> 21;

    size_t base = ((size_t)(b * Ts + t)) * (3 * Dd) + h * DHd;
    float qv = qkv[base + d];
    float kv = qkv[base + Dd + d];
    float vv = qkv[base + 2 * Dd + d];

    int d2 = (d < 32) ? d + 32 : d - 32;
    float sgn = (d < 32) ? -1.0f : 1.0f;
    float qp = qkv[base + d2] * sgn;
    float kp = qkv[base + Dd + d2] * sgn;

    int fidx = d & 31;
    float inv = (float)exp2(-(double)fidx / 32.0 * 13.287712379549449);
    float ang = (float)t * inv;
    float c, s;
    sincosf(ang, &s, &c);

    size_t oidx = (((size_t)(b * Hh + h)) * Ts + t) * DHd + d;
    qo[oidx] = qv * c + qp * s;
    ko[oidx] = kv * c + kp * s;
    vo[oidx] = vv;
}

// ---------------------------------------------------------------------------
// Tiled flash attention (fp32 CUDA cores):
//   64 queries x 64 keys per tile, 256 threads, 4x4 microtiles.
//   Thread (ty,tx): queries {ty+16i}, S keys {tx+16j}, O dims {tx*4+u}.
//   K tile XOR-swizzled for conflict-free column float4 reads.
//   P tile aliased onto K buffer -> 48KB static smem, 4 CTAs/SM.
// ---------------------------------------------------------------------------
__global__ __launch_bounds__(256) void flash_attn_kernel(
    const float* __restrict__ q, const float* __restrict__ k,
    const float* __restrict__ v, float* __restrict__ out) {

    __shared__ float Qs[64 * 64];   // [query][dim], natural
    __shared__ float Vs[64 * 64];   // [key][dim], natural
    __shared__ float KPs[64 * 64];  // K (XOR-swizzled) aliased with P [query][key]

    const int qb = (int)gridDim.x - 1 - (int)blockIdx.x;  // heavy blocks first
    const int h  = blockIdx.y;
    const int b  = blockIdx.z;
    const int tid = threadIdx.x;
    const int tx = tid & 15;
    const int ty = tid >> 4;
    const float scale = 0.125f;

    const size_t head_off = ((size_t)(b * Hh + h)) * Ts * DHd;
    const float4* q4g = (const float4*)(q + head_off);
    const float4* k4g = (const float4*)(k + head_off);
    const float4* v4g = (const float4*)(v + head_off);

    // load Q tile (64 x 64), natural layout
    #pragma unroll
    for (int it = 0; it < 4; it++) {
        int f = tid + it * 256;          // float4 index, row = f>>4, d4 = f&15
        ((float4*)Qs)[f] = q4g[(size_t)qb * 1024 + f];
    }

    float m_i[4], l_i[4];
    float o[4][4];
    #pragma unroll
    for (int i = 0; i < 4; i++) {
        m_i[i] = -INFINITY; l_i[i] = 0.0f;
        #pragma unroll
        for (int u = 0; u < 4; u++) o[i][u] = 0.0f;
    }

    for (int kt = 0; kt <= qb; kt++) {
        __syncthreads();   // previous-iter readers of KPs/Vs done
        // load K (swizzled) and V (natural)
        #pragma unroll
        for (int it = 0; it < 4; it++) {
            int f = tid + it * 256;
            int key = f >> 4, d4 = f & 15;
            ((float4*)KPs)[key * 16 + (d4 ^ (key & 15))] =
                k4g[(size_t)kt * 1024 + f];
            ((float4*)Vs)[f] = v4g[(size_t)kt * 1024 + f];
        }
        __syncthreads();

        // S = Q K^T (4x4 per thread)
        float s[4][4];
        #pragma unroll
        for (int i = 0; i < 4; i++)
            #pragma unroll
            for (int j = 0; j < 4; j++) s[i][j] = 0.0f;

        #pragma unroll
        for (int kk4 = 0; kk4 < 16; kk4++) {
            float4 qv4[4], kv4[4];
            #pragma unroll
            for (int i = 0; i < 4; i++)
                qv4[i] = ((const float4*)Qs)[(ty + 16 * i) * 16 + kk4];
            #pragma unroll
            for (int j = 0; j < 4; j++) {
                int row = tx + 16 * j;
                kv4[j] = ((const float4*)KPs)[row * 16 + (kk4 ^ (row & 15))];
            }
            #pragma unroll
            for (int i = 0; i < 4; i++)
                #pragma unroll
                for (int j = 0; j < 4; j++) {
                    s[i][j] = fmaf(qv4[i].x, kv4[j].x, s[i][j]);
                    s[i][j] = fmaf(qv4[i].y, kv4[j].y, s[i][j]);
                    s[i][j] = fmaf(qv4[i].z, kv4[j].z, s[i][j]);
                    s[i][j] = fmaf(qv4[i].w, kv4[j].w, s[i][j]);
                }
        }

        // scale + causal mask
        #pragma unroll
        for (int i = 0; i < 4; i++) {
            int qg = qb * 64 + ty + 16 * i;
            #pragma unroll
            for (int j = 0; j < 4; j++) {
                int kg = kt * 64 + tx + 16 * j;
                s[i][j] = (kg > qg) ? -1e30f : s[i][j] * scale;
            }
        }

        // online softmax: row reductions across the 16 tx lanes
        #pragma unroll
        for (int i = 0; i < 4; i++) {
            float mt = fmaxf(fmaxf(s[i][0], s[i][1]), fmaxf(s[i][2], s[i][3]));
            #pragma unroll
            for (int off = 1; off < 16; off <<= 1)
                mt = fmaxf(mt, __shfl_xor_sync(0xffffffffu, mt, off));
            float newm = fmaxf(m_i[i], mt);
            float corr = __expf(m_i[i] - newm);
            float ls = 0.0f;
            #pragma unroll
            for (int j = 0; j < 4; j++) {
                s[i][j] = __expf(s[i][j] - newm);   // s becomes p
                ls += s[i][j];
            }
            #pragma unroll
            for (int off = 1; off < 16; off <<= 1)
                ls += __shfl_xor_sync(0xffffffffu, ls, off);
            l_i[i] = l_i[i] * corr + ls;
            #pragma unroll
            for (int u = 0; u < 4; u++) o[i][u] *= corr;
            m_i[i] = newm;
        }

        __syncthreads();   // all threads done reading KPs as K
        // write P tile [query][key] into KPs
        #pragma unroll
        for (int i = 0; i < 4; i++)
            #pragma unroll
            for (int j = 0; j < 4; j++)
                KPs[(ty + 16 * i) * 64 + tx + 16 * j] = s[i][j];
        __syncthreads();

        // O += P @ V
        #pragma unroll
        for (int kk4 = 0; kk4 < 16; kk4++) {
            float4 p4[4], v4[4];
            #pragma unroll
            for (int i = 0; i < 4; i++)
                p4[i] = ((const float4*)KPs)[(ty + 16 * i) * 16 + kk4];
            #pragma unroll
            for (int c = 0; c < 4; c++)
                v4[c] = ((const float4*)Vs)[(kk4 * 4 + c) * 16 + tx];
            #pragma unroll
            for (int i = 0; i < 4; i++) {
                const float pc[4] = {p4[i].x, p4[i].y, p4[i].z, p4[i].w};
                #pragma unroll
                for (int c = 0; c < 4; c++) {
                    o[i][0] = fmaf(pc[c], v4[c].x, o[i][0]);
                    o[i][1] = fmaf(pc[c], v4[c].y, o[i][1]);
                    o[i][2] = fmaf(pc[c], v4[c].z, o[i][2]);
                    o[i][3] = fmaf(pc[c], v4[c].w, o[i][3]);
                }
            }
        }
    }

    // normalize + write out [B*T, D] with head offset
    #pragma unroll
    for (int i = 0; i < 4; i++) {
        float invl = 1.0f / l_i[i];
        int qg = qb * 64 + ty + 16 * i;
        float4 r = make_float4(o[i][0] * invl, o[i][1] * invl,
                               o[i][2] * invl, o[i][3] * invl);
        *(float4*)(out + ((size_t)(b * Ts + qg)) * Dd + h * DHd + tx * 4) = r;
    }
}

// ---------------------------------------------------------------------------
extern "C" void kernel_launch(void* const* d_in, const int* in_sizes, int n_in,
                              void* d_out, int out_size) {
    const float* x     = (const float*)d_in[0];
    const float* w_qkv = (const float*)d_in[1];
    const float* w_out = (const float*)d_in[2];
    float* out = (float*)d_out;

    float *qkv, *q, *k, *v, *attn;
    cudaGetSymbolAddress((void**)&qkv,  g_qkv);
    cudaGetSymbolAddress((void**)&q,    g_q);
    cudaGetSymbolAddress((void**)&k,    g_k);
    cudaGetSymbolAddress((void**)&v,    g_v);
    cudaGetSymbolAddress((void**)&attn, g_attn);

    sgemm128<<<dim3((3 * Dd) / 128, MROWS / 128), 256>>>(x, w_qkv, qkv,
                                                         MROWS, 3 * Dd, Dd);
    rope_split_kernel<<<(Bb * Hh * Ts * DHd) / 256, 256>>>(qkv, q, k, v);
    flash_attn_kernel<<<dim3(Ts / 64, Hh, Bb), 256>>>(q, k, v, attn);
    sgemm128<<<dim3(Dd / 128, MROWS / 128), 256>>>(attn, w_out, out,
                                                   MROWS, Dd, Dd);
}

// round 4
// speedup vs baseline: 1.5118x; 1.2697x over previous
#include <cuda_runtime.h>
#include <cuda_bf16.h>
#include <math.h>
#include <stdint.h>

#define Bb 2
#define Ts 2048
#define Dd 1024
#define Hh 16
#define DHd 64
#define MROWS (Bb*Ts)   // 4096

// ---------------------------------------------------------------------------
// Scratch (__device__ globals; allocation-free rule)
// ---------------------------------------------------------------------------
__device__ float g_qkv[(size_t)MROWS * 3 * Dd];          // [B*T, 3D]
__device__ float g_attn[(size_t)MROWS * Dd];             // [B*T, D]
__device__ __nv_bfloat16 g_qhi[(size_t)Bb*Hh*Ts*DHd];    // [b,h,t,d] (q*0.125)
__device__ __nv_bfloat16 g_qlo[(size_t)Bb*Hh*Ts*DHd];
__device__ __nv_bfloat16 g_khi[(size_t)Bb*Hh*Ts*DHd];    // [b,h,t,d]
__device__ __nv_bfloat16 g_klo[(size_t)Bb*Hh*Ts*DHd];
__device__ __nv_bfloat16 g_vthi[(size_t)Bb*Hh*DHd*Ts];   // [b,h,d,t] transposed
__device__ __nv_bfloat16 g_vtlo[(size_t)Bb*Hh*DHd*Ts];

// ---------------------------------------------------------------------------
// warp-mma helpers (baseline PTX, valid on plain sm_103 target)
// ---------------------------------------------------------------------------
__device__ __forceinline__ uint32_t smem_u32(const void* p) {
    uint32_t a;
    asm("{ .reg .u64 t; cvta.to.shared.u64 t, %1; cvt.u32.u64 %0, t; }"
        : "=r"(a) : "l"(p));
    return a;
}

__device__ __forceinline__ void mma_bf16(float* d, const uint32_t* a,
                                         uint32_t b0, uint32_t b1) {
    asm volatile(
        "mma.sync.aligned.m16n8k16.row.col.f32.bf16.bf16.f32 "
        "{%0,%1,%2,%3}, {%4,%5,%6,%7}, {%8,%9}, {%0,%1,%2,%3};"
        : "+f"(d[0]), "+f"(d[1]), "+f"(d[2]), "+f"(d[3])
        : "r"(a[0]), "r"(a[1]), "r"(a[2]), "r"(a[3]), "r"(b0), "r"(b1));
}

__device__ __forceinline__ void ldsm_x4(uint32_t addr, uint32_t* r) {
    asm volatile("ldmatrix.sync.aligned.m8n8.x4.shared.b16 {%0,%1,%2,%3}, [%4];"
        : "=r"(r[0]), "=r"(r[1]), "=r"(r[2]), "=r"(r[3]) : "r"(addr));
}

// pack two fp32 into bf16x2: lo -> lower half, hi -> upper half
__device__ __forceinline__ uint32_t packbf(float lo, float hi) {
    uint32_t r;
    asm("cvt.rn.bf16x2.f32 %0, %1, %2;" : "=r"(r) : "f"(hi), "f"(lo));
    return r;
}

// ---------------------------------------------------------------------------
// SGEMM (fp32, unchanged): C[M,N] = A[M,K] @ B[K,N]
// ---------------------------------------------------------------------------
__global__ __launch_bounds__(256) void sgemm128(const float* __restrict__ A,
                                                const float* __restrict__ Bw,
                                                float* __restrict__ C,
                                                int M, int N, int K) {
    constexpr int BM = 128, BN = 128, BK = 8;
    __shared__ float As[BK][BM];
    __shared__ float Bs[BK][BN];

    const int tid = threadIdx.x;
    const int bx = blockIdx.x, by = blockIdx.y;
    const int tx = tid & 15;
    const int ty = tid >> 4;

    const int arow = tid >> 1;
    const int acol = (tid & 1) * 4;
    const int brow = tid >> 5;
    const int bcol = (tid & 31) * 4;

    const float* Ap = A + (size_t)(by * BM + arow) * K + acol;
    const float* Bp = Bw + (size_t)brow * N + bx * BN + bcol;

    float acc[8][8];
    #pragma unroll
    for (int i = 0; i < 8; i++)
        #pragma unroll
        for (int j = 0; j < 8; j++) acc[i][j] = 0.0f;

    for (int k0 = 0; k0 < K; k0 += BK) {
        float4 a4 = *(const float4*)Ap;
        float4 b4 = *(const float4*)Bp;
        As[acol + 0][arow] = a4.x;
        As[acol + 1][arow] = a4.y;
        As[acol + 2][arow] = a4.z;
        As[acol + 3][arow] = a4.w;
        *(float4*)&Bs[brow][bcol] = b4;
        __syncthreads();

        #pragma unroll
        for (int kk = 0; kk < BK; kk++) {
            float am[8], bn[8];
            *(float4*)&am[0] = *(const float4*)&As[kk][ty * 8];
            *(float4*)&am[4] = *(const float4*)&As[kk][ty * 8 + 4];
            *(float4*)&bn[0] = *(const float4*)&Bs[kk][tx * 8];
            *(float4*)&bn[4] = *(const float4*)&Bs[kk][tx * 8 + 4];
            #pragma unroll
            for (int i = 0; i < 8; i++)
                #pragma unroll
                for (int j = 0; j < 8; j++)
                    acc[i][j] = fmaf(am[i], bn[j], acc[i][j]);
        }
        __syncthreads();
        Ap += BK;
        Bp += (size_t)BK * N;
    }

    float* Cp = C + (size_t)(by * BM + ty * 8) * N + bx * BN + tx * 8;
    #pragma unroll
    for (int i = 0; i < 8; i++) {
        *(float4*)(Cp + (size_t)i * N) =
            make_float4(acc[i][0], acc[i][1], acc[i][2], acc[i][3]);
        *(float4*)(Cp + (size_t)i * N + 4) =
            make_float4(acc[i][4], acc[i][5], acc[i][6], acc[i][7]);
    }
}

// ---------------------------------------------------------------------------
// RoPE + split into bf16 hi/lo operands (Q pre-scaled by 0.125; V transposed)
// ---------------------------------------------------------------------------
__global__ __launch_bounds__(256) void rope_split_kernel(
    const float* __restrict__ qkv,
    __nv_bfloat16* __restrict__ qhi, __nv_bfloat16* __restrict__ qlo,
    __nv_bfloat16* __restrict__ khi, __nv_bfloat16* __restrict__ klo,
    __nv_bfloat16* __restrict__ vthi, __nv_bfloat16* __restrict__ vtlo) {
    int idx = blockIdx.x * blockDim.x + threadIdx.x;
    int d = idx & 63;
    int t = (idx >> 6) & (Ts - 1);
    int h = (idx >> 17) & (Hh - 1);
    int b = idx >> 21;
    int bh = b * Hh + h;

    size_t base = ((size_t)(b * Ts + t)) * (3 * Dd) + h * DHd;
    float qv = qkv[base + d];
    float kv = qkv[base + Dd + d];
    float vv = qkv[base + 2 * Dd + d];

    int d2 = (d < 32) ? d + 32 : d - 32;
    float sgn = (d < 32) ? -1.0f : 1.0f;
    float qp = qkv[base + d2] * sgn;
    float kp = qkv[base + Dd + d2] * sgn;

    int fidx = d & 31;
    float inv = (float)exp2(-(double)fidx / 32.0 * 13.287712379549449);
    float ang = (float)t * inv;
    float c, s;
    sincosf(ang, &s, &c);

    float qr = (qv * c + qp * s) * 0.125f;   // fold softmax scale into q
    float kr = kv * c + kp * s;

    size_t oidx = (((size_t)bh) * Ts + t) * DHd + d;
    __nv_bfloat16 qh = __float2bfloat16_rn(qr);
    __nv_bfloat16 kh = __float2bfloat16_rn(kr);
    qhi[oidx] = qh; qlo[oidx] = __float2bfloat16_rn(qr - __bfloat162float(qh));
    khi[oidx] = kh; klo[oidx] = __float2bfloat16_rn(kr - __bfloat162float(kh));

    size_t vidx = (((size_t)bh) * DHd + d) * Ts + t;   // transposed
    __nv_bfloat16 vh = __float2bfloat16_rn(vv);
    vthi[vidx] = vh; vtlo[vidx] = __float2bfloat16_rn(vv - __bfloat162float(vh));
}

// ---------------------------------------------------------------------------
// Flash attention on warp-level bf16 HMMA (mma.sync m16n8k16), hi/lo split.
// CTA: 256 thr = 8 warps, 128 queries (16 rows/warp). K-tile = 64 keys.
// smem (32KB): Khi 0 | Klo 8K | VThi 16K | VTlo 24K  (Q staged there first)
// ---------------------------------------------------------------------------
__global__ __launch_bounds__(256) void attn_mma_kernel(
    const __nv_bfloat16* __restrict__ qhi, const __nv_bfloat16* __restrict__ qlo,
    const __nv_bfloat16* __restrict__ khi, const __nv_bfloat16* __restrict__ klo,
    const __nv_bfloat16* __restrict__ vthi, const __nv_bfloat16* __restrict__ vtlo,
    float* __restrict__ out) {
    __shared__ __align__(1024) char sm[32768];
    const int tid = threadIdx.x;
    const int w = tid >> 5, lane = tid & 31;
    const int qb = (int)gridDim.x - 1 - (int)blockIdx.x;   // heavy blocks first
    const int h = blockIdx.y, b = blockIdx.z;
    const int bh = b * Hh + h;
    const uint32_t sbase = smem_u32(sm);

    // ---- stage Q tile (hi @0, lo @16K), 128 rows x 128B, swizzled ----
    {
        const uint4* qh4 = (const uint4*)qhi + ((size_t)bh * Ts + qb * 128) * 8;
        const uint4* ql4 = (const uint4*)qlo + ((size_t)bh * Ts + qb * 128) * 8;
        #pragma unroll
        for (int i = 0; i < 4; i++) {
            int f = tid + i * 256;            // 0..1023
            int r = f >> 3, c = f & 7;
            uint32_t off = (r << 7) + (((uint32_t)(c ^ (r & 7))) << 4);
            *(uint4*)(sm + off)         = qh4[f];
            *(uint4*)(sm + 16384 + off) = ql4[f];
        }
    }
    __syncthreads();

    // ---- Q fragments (A-operand), 4 k-steps, hi+lo ----
    uint32_t qfh[4][4], qfl[4][4];
    #pragma unroll
    for (int ks = 0; ks < 4; ks++) {
        int r = w * 16 + (lane & 15);
        int chunk = ks * 2 + ((lane >> 4) & 1);
        uint32_t off = (r << 7) + (((uint32_t)(chunk ^ (r & 7))) << 4);
        ldsm_x4(sbase + off, qfh[ks]);
        ldsm_x4(sbase + 16384 + off, qfl[ks]);
    }
    __syncthreads();

    const int g = lane >> 2, tj = lane & 3;
    const int qg0 = qb * 128 + w * 16 + g;
    const int qg1 = qg0 + 8;

    float oa[8][4];
    #pragma unroll
    for (int nf = 0; nf < 8; nf++)
        #pragma unroll
        for (int e = 0; e < 4; e++) oa[nf][e] = 0.0f;
    float m_0 = -INFINITY, m_1 = -INFINITY, l_0 = 0.0f, l_1 = 0.0f;

    const uint4* kh4 = (const uint4*)khi + ((size_t)bh * Ts) * 8;
    const uint4* kl4 = (const uint4*)klo + ((size_t)bh * Ts) * 8;
    const uint4* vh4 = (const uint4*)vthi + ((size_t)bh * DHd) * 256;
    const uint4* vl4 = (const uint4*)vtlo + ((size_t)bh * DHd) * 256;

    const int nkt = 2 * qb + 2;
    for (int kt = 0; kt < nkt; kt++) {
        __syncthreads();
        // ---- stage K(hi/lo) and V^T(hi/lo) tiles, swizzled ----
        #pragma unroll
        for (int i = 0; i < 2; i++) {
            int f = tid + i * 256;            // 0..511
            int r = f >> 3, c = f & 7;
            uint32_t off = (r << 7) + (((uint32_t)(c ^ (r & 7))) << 4);
            size_t kidx = (size_t)(kt * 64 + r) * 8 + c;
            *(uint4*)(sm + off)         = kh4[kidx];
            *(uint4*)(sm + 8192 + off)  = kl4[kidx];
            size_t vidx = (size_t)r * 256 + kt * 8 + c;
            *(uint4*)(sm + 16384 + off) = vh4[vidx];
            *(uint4*)(sm + 24576 + off) = vl4[vidx];
        }
        __syncthreads();

        // ---- S = Q K^T (3-term hi/lo split) ----
        float sa[8][4];
        #pragma unroll
        for (int nf = 0; nf < 8; nf++)
            #pragma unroll
            for (int e = 0; e < 4; e++) sa[nf][e] = 0.0f;

        #pragma unroll
        for (int k2 = 0; k2 < 2; k2++) {
            #pragma unroll
            for (int nf = 0; nf < 8; nf++) {
                int rr = nf * 8 + (lane & 7);
                int chunk = k2 * 4 + ((lane >> 3) & 3);
                uint32_t off = (rr << 7) + (((uint32_t)(chunk ^ (rr & 7))) << 4);
                uint32_t bhv[4], blv[4];
                ldsm_x4(sbase + off, bhv);
                ldsm_x4(sbase + 8192 + off, blv);
                mma_bf16(sa[nf], qfh[2 * k2],     bhv[0], bhv[1]);
                mma_bf16(sa[nf], qfh[2 * k2],     blv[0], blv[1]);
                mma_bf16(sa[nf], qfl[2 * k2],     bhv[0], bhv[1]);
                mma_bf16(sa[nf], qfh[2 * k2 + 1], bhv[2], bhv[3]);
                mma_bf16(sa[nf], qfh[2 * k2 + 1], blv[2], blv[3]);
                mma_bf16(sa[nf], qfl[2 * k2 + 1], bhv[2], bhv[3]);
            }
        }

        // ---- causal mask + online softmax (registers only) ----
        float tmax0 = -INFINITY, tmax1 = -INFINITY;
        #pragma unroll
        for (int nf = 0; nf < 8; nf++) {
            int kg = kt * 64 + nf * 8 + 2 * tj;
            if (kg     > qg0) sa[nf][0] = -INFINITY;
            if (kg + 1 > qg0) sa[nf][1] = -INFINITY;
            if (kg     > qg1) sa[nf][2] = -INFINITY;
            if (kg + 1 > qg1) sa[nf][3] = -INFINITY;
            tmax0 = fmaxf(tmax0, fmaxf(sa[nf][0], sa[nf][1]));
            tmax1 = fmaxf(tmax1, fmaxf(sa[nf][2], sa[nf][3]));
        }
        tmax0 = fmaxf(tmax0, __shfl_xor_sync(0xffffffffu, tmax0, 1));
        tmax0 = fmaxf(tmax0, __shfl_xor_sync(0xffffffffu, tmax0, 2));
        tmax1 = fmaxf(tmax1, __shfl_xor_sync(0xffffffffu, tmax1, 1));
        tmax1 = fmaxf(tmax1, __shfl_xor_sync(0xffffffffu, tmax1, 2));

        float mn0 = fmaxf(m_0, tmax0), mn1 = fmaxf(m_1, tmax1);
        float c0 = __expf(m_0 - mn0), c1 = __expf(m_1 - mn1);
        m_0 = mn0; m_1 = mn1;
        l_0 *= c0; l_1 *= c1;
        #pragma unroll
        for (int nf = 0; nf < 8; nf++) {
            oa[nf][0] *= c0; oa[nf][1] *= c0;
            oa[nf][2] *= c1; oa[nf][3] *= c1;
        }

        // P = exp(S - m), packed into A-fragments (hi + residual lo)
        uint32_t ph[4][4], pl[4][4];
        #pragma unroll
        for (int nf = 0; nf < 8; nf++) {
            float p0 = __expf(sa[nf][0] - m_0);
            float p1 = __expf(sa[nf][1] - m_0);
            float p2 = __expf(sa[nf][2] - m_1);
            float p3 = __expf(sa[nf][3] - m_1);
            l_0 += p0 + p1; l_1 += p2 + p3;
            uint32_t u01 = packbf(p0, p1);
            uint32_t u23 = packbf(p2, p3);
            float h0 = __uint_as_float(u01 << 16);
            float h1 = __uint_as_float(u01 & 0xffff0000u);
            float h2 = __uint_as_float(u23 << 16);
            float h3 = __uint_as_float(u23 & 0xffff0000u);
            int ks = nf >> 1, hf = nf & 1;
            ph[ks][hf * 2 + 0] = u01;
            ph[ks][hf * 2 + 1] = u23;
            pl[ks][hf * 2 + 0] = packbf(p0 - h0, p1 - h1);
            pl[ks][hf * 2 + 1] = packbf(p2 - h2, p3 - h3);
        }

        // ---- O += P V (3-term hi/lo split) ----
        #pragma unroll
        for (int k2 = 0; k2 < 2; k2++) {
            #pragma unroll
            for (int nf = 0; nf < 8; nf++) {
                int rr = nf * 8 + (lane & 7);
                int chunk = k2 * 4 + ((lane >> 3) & 3);
                uint32_t off = (rr << 7) + (((uint32_t)(chunk ^ (rr & 7))) << 4);
                uint32_t bhv[4], blv[4];
                ldsm_x4(sbase + 16384 + off, bhv);
                ldsm_x4(sbase + 24576 + off, blv);
                mma_bf16(oa[nf], ph[2 * k2],     bhv[0], bhv[1]);
                mma_bf16(oa[nf], ph[2 * k2],     blv[0], blv[1]);
                mma_bf16(oa[nf], pl[2 * k2],     bhv[0], bhv[1]);
                mma_bf16(oa[nf], ph[2 * k2 + 1], bhv[2], bhv[3]);
                mma_bf16(oa[nf], ph[2 * k2 + 1], blv[2], blv[3]);
                mma_bf16(oa[nf], pl[2 * k2 + 1], bhv[2], bhv[3]);
            }
        }
    }

    // ---- epilogue ----
    l_0 += __shfl_xor_sync(0xffffffffu, l_0, 1);
    l_0 += __shfl_xor_sync(0xffffffffu, l_0, 2);
    l_1 += __shfl_xor_sync(0xffffffffu, l_1, 1);
    l_1 += __shfl_xor_sync(0xffffffffu, l_1, 2);
    float i0 = 1.0f / l_0, i1 = 1.0f / l_1;

    float* o0 = out + ((size_t)(b * Ts) + qb * 128 + w * 16 + g) * Dd + h * DHd;
    float* o1 = o0 + (size_t)8 * Dd;
    #pragma unroll
    for (int nf = 0; nf < 8; nf++) {
        int col = nf * 8 + 2 * tj;
        *(float2*)(o0 + col) = make_float2(oa[nf][0] * i0, oa[nf][1] * i0);
        *(float2*)(o1 + col) = make_float2(oa[nf][2] * i1, oa[nf][3] * i1);
    }
}

// ---------------------------------------------------------------------------
extern "C" void kernel_launch(void* const* d_in, const int* in_sizes, int n_in,
                              void* d_out, int out_size) {
    const float* x     = (const float*)d_in[0];
    const float* w_qkv = (const float*)d_in[1];
    const float* w_out = (const float*)d_in[2];
    float* out = (float*)d_out;

    float *qkv, *attn;
    __nv_bfloat16 *qhi, *qlo, *khi, *klo, *vthi, *vtlo;
    cudaGetSymbolAddress((void**)&qkv,  g_qkv);
    cudaGetSymbolAddress((void**)&attn, g_attn);
    cudaGetSymbolAddress((void**)&qhi,  g_qhi);
    cudaGetSymbolAddress((void**)&qlo,  g_qlo);
    cudaGetSymbolAddress((void**)&khi,  g_khi);
    cudaGetSymbolAddress((void**)&klo,  g_klo);
    cudaGetSymbolAddress((void**)&vthi, g_vthi);
    cudaGetSymbolAddress((void**)&vtlo, g_vtlo);

    sgemm128<<<dim3((3 * Dd) / 128, MROWS / 128), 256>>>(x, w_qkv, qkv,
                                                         MROWS, 3 * Dd, Dd);
    rope_split_kernel<<<(Bb * Hh * Ts * DHd) / 256, 256>>>(
        qkv, qhi, qlo, khi, klo, vthi, vtlo);
    attn_mma_kernel<<<dim3(Ts / 128, Hh, Bb), 256>>>(
        qhi, qlo, khi, klo, vthi, vtlo, attn);
    sgemm128<<<dim3(Dd / 128, MROWS / 128), 256>>>(attn, w_out, out,
                                                   MROWS, Dd, Dd);
}